// round 13
// baseline (speedup 1.0000x reference)
#include <cuda_runtime.h>
#include <cuda_bf16.h>
#include <cstdint>

// ---------------------------------------------------------------------------
// RNN: h_t = tanh(x_t @ Wx + h_{t-1} @ Wh),  B=32, L=512, D=1024, fp32.
// Phase 1: xp = x @ Wx via mma.sync 3xTF32, cp.async double-buffered, 2 CTA/SM.
// Phase 2: persistent recurrence; warp-local h staging (syncwarp only),
//          per-block flag barrier (parallel STG arrive + warp-parallel poll).
// ---------------------------------------------------------------------------

#define B_DIM 32
#define L_DIM 512
#define D_DIM 1024
#define NB 128
#define TPB 256

typedef unsigned long long u64;

// per-group flags: [bq][block-in-group * 8] (32B spacing -> parallel sectors)
__device__ unsigned g_flags2[4][256];

__global__ void init_flags_kernel() {
    int i = blockIdx.x * blockDim.x + threadIdx.x;
    if (i < 4 * 256) ((unsigned*)g_flags2)[i] = 0u;
}

__device__ __forceinline__ u64 pack2(float lo, float hi) {
    u64 r;
    asm("mov.b64 %0, {%1, %2};" : "=l"(r) : "f"(lo), "f"(hi));
    return r;
}
__device__ __forceinline__ void unpack2(u64 v, float& lo, float& hi) {
    asm("mov.b64 {%0, %1}, %2;" : "=f"(lo), "=f"(hi) : "l"(v));
}
__device__ __forceinline__ void ffma2(u64& d, u64 a, u64 b) {
    asm("fma.rn.f32x2 %0, %1, %2, %0;" : "+l"(d) : "l"(a), "l"(b));
}

// tf32 split: hi = tf32(v), lo = tf32(v - float(hi))
__device__ __forceinline__ void tf32_split(float v, uint32_t& hi, uint32_t& lo) {
    asm("cvt.rna.tf32.f32 %0, %1;" : "=r"(hi) : "f"(v));
    float r = v - __uint_as_float(hi);
    asm("cvt.rna.tf32.f32 %0, %1;" : "=r"(lo) : "f"(r));
}

__device__ __forceinline__ void mma_tf32(float* d, const uint32_t* a, const uint32_t* b) {
    asm("mma.sync.aligned.m16n8k8.row.col.f32.tf32.tf32.f32 "
        "{%0,%1,%2,%3}, {%4,%5,%6,%7}, {%8,%9}, {%0,%1,%2,%3};"
        : "+f"(d[0]), "+f"(d[1]), "+f"(d[2]), "+f"(d[3])
        : "r"(a[0]), "r"(a[1]), "r"(a[2]), "r"(a[3]), "r"(b[0]), "r"(b[1]));
}

__device__ __forceinline__ uint32_t smem_u32p(const void* p) {
    uint32_t a;
    asm("{ .reg .u64 t; cvta.to.shared.u64 t, %1; cvt.u32.u64 %0, t; }" : "=r"(a) : "l"(p));
    return a;
}
__device__ __forceinline__ void cp16(uint32_t dst, const void* src) {
    asm volatile("cp.async.cg.shared.global [%0], [%1], 16;" :: "r"(dst), "l"(src));
}

// ---------------------------------------------------------------------------
// Phase 1 (unchanged from R12): 3xTF32 mma.sync, cp.async, 2 CTAs/SM.
// ---------------------------------------------------------------------------
#define KT 32
#define AST 36
#define BST 136
#define ABUF_F (128 * AST)
#define BBUF_F (KT * BST)
#define P1_SMEM_BYTES ((2 * ABUF_F + 2 * BBUF_F) * 4)

__global__ __launch_bounds__(256, 2) void gemm_mma_kernel(
    const float* __restrict__ A, const float* __restrict__ W,
    float* __restrict__ C)
{
    extern __shared__ __align__(16) float sm1[];
    float* As = sm1;
    float* Bs = sm1 + 2 * ABUF_F;

    const int tid  = threadIdx.x;
    const int warp = tid >> 5;
    const int lane = tid & 31;
    const int wm = warp >> 2;
    const int wn = warp & 3;
    const int m0 = blockIdx.y * 128;
    const int n0 = blockIdx.x * 128;

    const int lr = lane >> 2;
    const int lc = lane & 3;

    const uint32_t asb[2] = { smem_u32p(As), smem_u32p(As + ABUF_F) };
    const uint32_t bsb[2] = { smem_u32p(Bs), smem_u32p(Bs + BBUF_F) };

    float acc[4][4][4];
#pragma unroll
    for (int i = 0; i < 4; ++i)
#pragma unroll
        for (int j = 0; j < 4; ++j)
#pragma unroll
            for (int p = 0; p < 4; ++p) acc[i][j][p] = 0.0f;

    auto issue_tile = [&](int buf, int k0) {
#pragma unroll
        for (int it = 0; it < 4; ++it) {
            int idx = it * 256 + tid;
            int r = idx >> 3, k4 = idx & 7;
            cp16(asb[buf] + (uint32_t)(r * AST + k4 * 4) * 4,
                 A + (size_t)(m0 + r) * D_DIM + k0 + k4 * 4);
        }
#pragma unroll
        for (int it = 0; it < 4; ++it) {
            int idx = it * 256 + tid;
            int kr = idx >> 5, n4 = idx & 31;
            cp16(bsb[buf] + (uint32_t)(kr * BST + n4 * 4) * 4,
                 W + (size_t)(k0 + kr) * D_DIM + n0 + n4 * 4);
        }
        asm volatile("cp.async.commit_group;");
    };

    issue_tile(0, 0);

    int cur = 0;
    for (int kt = 0; kt < D_DIM / KT; ++kt) {
        const bool more = (kt + 1) < (D_DIM / KT);
        if (more) {
            issue_tile(cur ^ 1, (kt + 1) * KT);
            asm volatile("cp.async.wait_group 1;");
        } else {
            asm volatile("cp.async.wait_group 0;");
        }
        __syncthreads();

        const float* as = As + cur * ABUF_F;
        const float* bs = Bs + cur * BBUF_F;
#pragma unroll
        for (int ks = 0; ks < 4; ++ks) {
            const int kbase = ks * 8;
            uint32_t ah[4][4], al[4][4];
#pragma unroll
            for (int fm = 0; fm < 4; ++fm) {
                const int rbase = wm * 64 + fm * 16;
                float a0 = as[(rbase + lr) * AST + kbase + lc];
                float a1 = as[(rbase + lr + 8) * AST + kbase + lc];
                float a2 = as[(rbase + lr) * AST + kbase + lc + 4];
                float a3 = as[(rbase + lr + 8) * AST + kbase + lc + 4];
                tf32_split(a0, ah[fm][0], al[fm][0]);
                tf32_split(a1, ah[fm][1], al[fm][1]);
                tf32_split(a2, ah[fm][2], al[fm][2]);
                tf32_split(a3, ah[fm][3], al[fm][3]);
            }
            uint32_t bh[4][2], bl[4][2];
#pragma unroll
            for (int fn = 0; fn < 4; ++fn) {
                const int nbase = wn * 32 + fn * 8;
                float b0 = bs[(kbase + lc) * BST + nbase + lr];
                float b1 = bs[(kbase + lc + 4) * BST + nbase + lr];
                tf32_split(b0, bh[fn][0], bl[fn][0]);
                tf32_split(b1, bh[fn][1], bl[fn][1]);
            }
#pragma unroll
            for (int fm = 0; fm < 4; ++fm)
#pragma unroll
                for (int fn = 0; fn < 4; ++fn) {
                    mma_tf32(acc[fm][fn], ah[fm], bl[fn]);
                    mma_tf32(acc[fm][fn], al[fm], bh[fn]);
                    mma_tf32(acc[fm][fn], ah[fm], bh[fn]);
                }
        }
        __syncthreads();
        cur ^= 1;
    }

#pragma unroll
    for (int fm = 0; fm < 4; ++fm) {
        const int rbase = m0 + wm * 64 + fm * 16 + lr;
#pragma unroll
        for (int fn = 0; fn < 4; ++fn) {
            const int cbase = n0 + wn * 32 + fn * 8 + lc * 2;
            *(float2*)(C + (size_t)rbase * D_DIM + cbase) =
                make_float2(acc[fm][fn][0], acc[fm][fn][1]);
            *(float2*)(C + (size_t)(rbase + 8) * D_DIM + cbase) =
                make_float2(acc[fm][fn][2], acc[fm][fn][3]);
        }
    }
}

// ---------------------------------------------------------------------------
// Phase 2: persistent recurrence (256 threads).
// bid -> (bq = bid>>5 owns b in [bq*8, bq*8+8), jg = bid&31 owns 32 columns).
// Thread: jq = lane&7 -> 4 columns; kc = warp*4 + (lane>>3) -> 32 k.
// Staging: warp w loads k-slice [w*128,(w+1)*128) of all 8 rows (its own
//          consumption set) -> __syncwarp only, no block sync.
// Barrier: per-block flag STG.release (parallel) + warp-0 parallel poll.
// ---------------------------------------------------------------------------
#define HROW_F 1152
#define PART_STRIDE 36
#define HS_FLOATS (8 * HROW_F)
#define PART_OFF HS_FLOATS
#define PART_FLOATS (8 * 32 * PART_STRIDE)
#define SMEM2_FLOATS (PART_OFF + PART_FLOATS)

__global__ __launch_bounds__(TPB, 1) void rnn_steps_kernel(
    float* __restrict__ out,          // [B, L, D]: holds xp, overwritten by h
    const float* __restrict__ h0,     // [B, D]
    const float* __restrict__ Wh)     // [D, D]
{
    extern __shared__ __align__(16) float smem[];
    float* hs   = smem;
    float* part = smem + PART_OFF;

    const int tid  = threadIdx.x;
    const int warp = tid >> 5;
    const int lane = tid & 31;
    const int bid  = blockIdx.x;
    const int jg = bid & 31, bq = bid >> 5;
    const int j0 = jg * 32, b0 = bq * 8;
    const int jq = lane & 7;
    const int kc = (warp << 2) | (lane >> 3);
    const int kb = kc * 32;
    const int kcs = kc ^ (jq << 2);            // swizzled partial column

    u64 wreg[4][16];
#pragma unroll
    for (int jl = 0; jl < 4; ++jl) {
        const int jcol = j0 + jq * 4 + jl;
#pragma unroll
        for (int kk = 0; kk < 16; ++kk) {
            float w0 = Wh[(size_t)(kb + 2 * kk)     * D_DIM + jcol];
            float w1 = Wh[(size_t)(kb + 2 * kk + 1) * D_DIM + jcol];
            wreg[jl][kk] = pack2(w0, w1);
        }
    }

    const size_t obase = ((size_t)(b0 + warp) * L_DIM) * D_DIM + j0 + lane;
    unsigned* myflag  = &g_flags2[bq][jg * 8];
    const unsigned* pollflag = &g_flags2[bq][lane * 8];

    // staging destination for this warp's k-slice
    const int sidx = warp * 32 + lane;                   // float4 index in row
    float* sdst = hs + (sidx >> 3) * 36 + (sidx & 7) * 4;

    float xp = out[obase];

    for (int t = 0; t < L_DIM; ++t) {
        const size_t orow = obase + (size_t)t * D_DIM;

        // ---- warp-local staging: this warp's k-slice of all 8 rows ----
        {
            const float* src0;
            size_t rstr;
            if (t == 0) { src0 = h0 + (size_t)b0 * D_DIM; rstr = D_DIM; }
            else        { src0 = out + ((size_t)b0 * L_DIM + (t - 1)) * D_DIM;
                          rstr = (size_t)L_DIM * D_DIM; }
            const float* sp = src0 + warp * 128 + lane * 4;
            float4 v[8];
#pragma unroll
            for (int b = 0; b < 8; ++b)
                v[b] = __ldcg((const float4*)(sp + b * rstr));
#pragma unroll
            for (int b = 0; b < 8; ++b)
                *(float4*)(sdst + b * HROW_F) = v[b];
        }
        __syncwarp();

        // early xp prefetch for t+1 (slot written only by this thread at t+1)
        float xp_next = 0.0f;
        if (t + 1 < L_DIM) xp_next = out[orow + D_DIM];

        u64 acc[8][4];
#pragma unroll
        for (int b = 0; b < 8; ++b)
#pragma unroll
            for (int jl = 0; jl < 4; ++jl) acc[b][jl] = 0ull;

#pragma unroll
        for (int b = 0; b < 8; ++b) {
            const ulonglong2* hb = (const ulonglong2*)(hs + b * HROW_F + kc * 36);
#pragma unroll
            for (int i = 0; i < 8; ++i) {
                ulonglong2 hp = hb[i];
                ffma2(acc[b][0], hp.x, wreg[0][2 * i]);
                ffma2(acc[b][1], hp.x, wreg[1][2 * i]);
                ffma2(acc[b][2], hp.x, wreg[2][2 * i]);
                ffma2(acc[b][3], hp.x, wreg[3][2 * i]);
                ffma2(acc[b][0], hp.y, wreg[0][2 * i + 1]);
                ffma2(acc[b][1], hp.y, wreg[1][2 * i + 1]);
                ffma2(acc[b][2], hp.y, wreg[2][2 * i + 1]);
                ffma2(acc[b][3], hp.y, wreg[3][2 * i + 1]);
            }
        }

#pragma unroll
        for (int b = 0; b < 8; ++b)
#pragma unroll
            for (int jl = 0; jl < 4; ++jl) {
                float lo, hi;
                unpack2(acc[b][jl], lo, hi);
                part[(b * 32 + jq * 4 + jl) * PART_STRIDE + kcs] = lo + hi;
            }

        __syncthreads();

        float s = xp;
        const float* pr = part + (warp * 32 + lane) * PART_STRIDE;
#pragma unroll
        for (int g = 0; g < 8; ++g) {
            float4 p = *(const float4*)(pr + g * 4);
            s += (p.x + p.y) + (p.z + p.w);
        }
        out[orow] = tanhf(s);

        if (t + 1 < L_DIM) {
            __syncthreads();   // all STG issued; also protects hs/part reuse
            if (tid == 0) {
                asm volatile("st.release.gpu.u32 [%0], %1;"
                             :: "l"(myflag), "r"((unsigned)(t + 1)) : "memory");
            }
            if (warp == 0) {
                const unsigned target = (unsigned)(t + 1);
                unsigned v;
                int spins = 0;
                do {
                    asm volatile("ld.acquire.gpu.u32 %0, [%1];"
                                 : "=r"(v) : "l"(pollflag) : "memory");
                    if (++spins > 4 && v < target) __nanosleep(32);
                } while (!__all_sync(0xffffffffu, v >= target));
            }
            __syncthreads();
        }

        xp = xp_next;
    }
}

// ---------------------------------------------------------------------------
extern "C" void kernel_launch(void* const* d_in, const int* in_sizes, int n_in,
                              void* d_out, int out_size)
{
    (void)in_sizes; (void)n_in; (void)out_size;
    const float* x  = (const float*)d_in[0];
    const float* h0 = (const float*)d_in[1];
    const float* Wx = (const float*)d_in[2];
    const float* Wh = (const float*)d_in[3];
    float* out = (float*)d_out;

    // phase 1: 3xTF32 tensor-core GEMM (cp.async, 2 CTAs/SM)
    cudaFuncSetAttribute(gemm_mma_kernel,
                         cudaFuncAttributeMaxDynamicSharedMemorySize,
                         P1_SMEM_BYTES);
    dim3 g1(D_DIM / 128, (B_DIM * L_DIM) / 128);
    gemm_mma_kernel<<<g1, 256, P1_SMEM_BYTES>>>(x, Wx, out);

    // phase 2: persistent recurrence
    init_flags_kernel<<<1, 1024>>>();
    size_t smem_bytes = (size_t)SMEM2_FLOATS * sizeof(float);
    cudaFuncSetAttribute(rnn_steps_kernel,
                         cudaFuncAttributeMaxDynamicSharedMemorySize,
                         (int)smem_bytes);
    rnn_steps_kernel<<<NB, TPB, smem_bytes>>>(out, h0, Wh);
}

// round 14
// speedup vs baseline: 1.3261x; 1.3261x over previous
#include <cuda_runtime.h>
#include <cuda_bf16.h>
#include <cstdint>

// ---------------------------------------------------------------------------
// RNN: h_t = tanh(x_t @ Wx + h_{t-1} @ Wh),  B=32, L=512, D=1024, fp32.
// Phase 1: xp = x @ Wx via mma.sync 3xTF32, cp.async double-buffered,
//          hoisted staging addresses, 2 CTAs/SM.
// Phase 2: persistent recurrence (R12 design: counter barrier per group,
//          swizzled partials, early xp prefetch, no final barrier).
// ---------------------------------------------------------------------------

#define B_DIM 32
#define L_DIM 512
#define D_DIM 1024
#define NB 128
#define TPB 256

typedef unsigned long long u64;

__device__ unsigned g_ctrs[4];

__global__ void init_flags_kernel() {
    if (threadIdx.x < 4) g_ctrs[threadIdx.x] = 0u;
}

__device__ __forceinline__ u64 pack2(float lo, float hi) {
    u64 r;
    asm("mov.b64 %0, {%1, %2};" : "=l"(r) : "f"(lo), "f"(hi));
    return r;
}
__device__ __forceinline__ void unpack2(u64 v, float& lo, float& hi) {
    asm("mov.b64 {%0, %1}, %2;" : "=f"(lo), "=f"(hi) : "l"(v));
}
__device__ __forceinline__ void ffma2(u64& d, u64 a, u64 b) {
    asm("fma.rn.f32x2 %0, %1, %2, %0;" : "+l"(d) : "l"(a), "l"(b));
}

// tf32 split: hi = tf32(v), lo = tf32(v - float(hi))
__device__ __forceinline__ void tf32_split(float v, uint32_t& hi, uint32_t& lo) {
    asm("cvt.rna.tf32.f32 %0, %1;" : "=r"(hi) : "f"(v));
    float r = v - __uint_as_float(hi);
    asm("cvt.rna.tf32.f32 %0, %1;" : "=r"(lo) : "f"(r));
}

__device__ __forceinline__ void mma_tf32(float* d, const uint32_t* a, const uint32_t* b) {
    asm("mma.sync.aligned.m16n8k8.row.col.f32.tf32.tf32.f32 "
        "{%0,%1,%2,%3}, {%4,%5,%6,%7}, {%8,%9}, {%0,%1,%2,%3};"
        : "+f"(d[0]), "+f"(d[1]), "+f"(d[2]), "+f"(d[3])
        : "r"(a[0]), "r"(a[1]), "r"(a[2]), "r"(a[3]), "r"(b[0]), "r"(b[1]));
}

__device__ __forceinline__ uint32_t smem_u32p(const void* p) {
    uint32_t a;
    asm("{ .reg .u64 t; cvta.to.shared.u64 t, %1; cvt.u32.u64 %0, t; }" : "=r"(a) : "l"(p));
    return a;
}
__device__ __forceinline__ void cp16(uint32_t dst, const void* src) {
    asm volatile("cp.async.cg.shared.global [%0], [%1], 16;" :: "r"(dst), "l"(src));
}

// ---------------------------------------------------------------------------
// Phase 1: C[16384,1024] = A[16384,1024] * W[1024,1024], 3xTF32 mma.sync.
// Block tile 128x128, 8 warps (2 x 4), warp tile 64x32, K-tile 32.
// A in SMEM [m][k] stride 36; B in SMEM [k][n] stride 136 (both conflict-free).
// Staging addresses hoisted: src pointers advance by KT / KT*D per tile.
// ---------------------------------------------------------------------------
#define KT 32
#define AST 36
#define BST 136
#define ABUF_F (128 * AST)
#define BBUF_F (KT * BST)
#define P1_SMEM_BYTES ((2 * ABUF_F + 2 * BBUF_F) * 4)

__global__ __launch_bounds__(256, 2) void gemm_mma_kernel(
    const float* __restrict__ A, const float* __restrict__ W,
    float* __restrict__ C)
{
    extern __shared__ __align__(16) float sm1[];
    float* As = sm1;
    float* Bs = sm1 + 2 * ABUF_F;

    const int tid  = threadIdx.x;
    const int warp = tid >> 5;
    const int lane = tid & 31;
    const int wm = warp >> 2;
    const int wn = warp & 3;
    const int m0 = blockIdx.y * 128;
    const int n0 = blockIdx.x * 128;

    const int lr = lane >> 2;
    const int lc = lane & 3;

    const uint32_t asb[2] = { smem_u32p(As), smem_u32p(As + ABUF_F) };
    const uint32_t bsb[2] = { smem_u32p(Bs), smem_u32p(Bs + BBUF_F) };

    // hoisted staging addresses: per-thread 4 A-chunks + 4 B-chunks
    const float* aSrc[4];
    const float* bSrc[4];
    uint32_t aOff[4], bOff[4];
#pragma unroll
    for (int it = 0; it < 4; ++it) {
        int idx = it * 256 + tid;
        int r = idx >> 3, k4 = idx & 7;
        aSrc[it] = A + (size_t)(m0 + r) * D_DIM + k4 * 4;
        aOff[it] = (uint32_t)(r * AST + k4 * 4) * 4;
        int kr = idx >> 5, n4 = idx & 31;
        bSrc[it] = W + (size_t)kr * D_DIM + n0 + n4 * 4;
        bOff[it] = (uint32_t)(kr * BST + n4 * 4) * 4;
    }

    float acc[4][4][4];
#pragma unroll
    for (int i = 0; i < 4; ++i)
#pragma unroll
        for (int j = 0; j < 4; ++j)
#pragma unroll
            for (int p = 0; p < 4; ++p) acc[i][j][p] = 0.0f;

    auto issue_tile = [&](int buf) {
#pragma unroll
        for (int it = 0; it < 4; ++it) {
            cp16(asb[buf] + aOff[it], aSrc[it]);
            aSrc[it] += KT;
        }
#pragma unroll
        for (int it = 0; it < 4; ++it) {
            cp16(bsb[buf] + bOff[it], bSrc[it]);
            bSrc[it] += (size_t)KT * D_DIM;
        }
        asm volatile("cp.async.commit_group;");
    };

    issue_tile(0);

    int cur = 0;
    for (int kt = 0; kt < D_DIM / KT; ++kt) {
        const bool more = (kt + 1) < (D_DIM / KT);
        if (more) {
            issue_tile(cur ^ 1);
            asm volatile("cp.async.wait_group 1;");
        } else {
            asm volatile("cp.async.wait_group 0;");
        }
        __syncthreads();

        const float* as = As + cur * ABUF_F;
        const float* bs = Bs + cur * BBUF_F;
#pragma unroll
        for (int ks = 0; ks < 4; ++ks) {
            const int kbase = ks * 8;
            uint32_t ah[4][4], al[4][4];
#pragma unroll
            for (int fm = 0; fm < 4; ++fm) {
                const int rbase = wm * 64 + fm * 16;
                float a0 = as[(rbase + lr) * AST + kbase + lc];
                float a1 = as[(rbase + lr + 8) * AST + kbase + lc];
                float a2 = as[(rbase + lr) * AST + kbase + lc + 4];
                float a3 = as[(rbase + lr + 8) * AST + kbase + lc + 4];
                tf32_split(a0, ah[fm][0], al[fm][0]);
                tf32_split(a1, ah[fm][1], al[fm][1]);
                tf32_split(a2, ah[fm][2], al[fm][2]);
                tf32_split(a3, ah[fm][3], al[fm][3]);
            }
            uint32_t bh[4][2], bl[4][2];
#pragma unroll
            for (int fn = 0; fn < 4; ++fn) {
                const int nbase = wn * 32 + fn * 8;
                float b0 = bs[(kbase + lc) * BST + nbase + lr];
                float b1 = bs[(kbase + lc + 4) * BST + nbase + lr];
                tf32_split(b0, bh[fn][0], bl[fn][0]);
                tf32_split(b1, bh[fn][1], bl[fn][1]);
            }
#pragma unroll
            for (int fm = 0; fm < 4; ++fm)
#pragma unroll
                for (int fn = 0; fn < 4; ++fn) {
                    mma_tf32(acc[fm][fn], ah[fm], bl[fn]);
                    mma_tf32(acc[fm][fn], al[fm], bh[fn]);
                    mma_tf32(acc[fm][fn], ah[fm], bh[fn]);
                }
        }
        __syncthreads();
        cur ^= 1;
    }

#pragma unroll
    for (int fm = 0; fm < 4; ++fm) {
        const int rbase = m0 + wm * 64 + fm * 16 + lr;
#pragma unroll
        for (int fn = 0; fn < 4; ++fn) {
            const int cbase = n0 + wn * 32 + fn * 8 + lc * 2;
            *(float2*)(C + (size_t)rbase * D_DIM + cbase) =
                make_float2(acc[fm][fn][0], acc[fm][fn][1]);
            *(float2*)(C + (size_t)(rbase + 8) * D_DIM + cbase) =
                make_float2(acc[fm][fn][2], acc[fm][fn][3]);
        }
    }
}

// ---------------------------------------------------------------------------
// Phase 2: persistent recurrence (R12 version, 256 threads).
// bid -> (bq = bid>>5 owns b in [bq*8, bq*8+8), jg = bid&31 owns 32 columns).
// Thread: jq = lane&7 -> 4 columns; kc = warp*4 + (lane>>3) -> 32 k.
// Partial STS column-swizzled (kc ^ (jq<<2)) -> conflict-free.
// Counter barrier per group; aggressive poll before sleep.
// ---------------------------------------------------------------------------
#define HROW_F 1152
#define PART_STRIDE 36
#define HS_FLOATS (8 * HROW_F)
#define PART_OFF HS_FLOATS
#define PART_FLOATS (8 * 32 * PART_STRIDE)
#define SMEM2_FLOATS (PART_OFF + PART_FLOATS)

__global__ __launch_bounds__(TPB, 1) void rnn_steps_kernel(
    float* __restrict__ out,          // [B, L, D]: holds xp, overwritten by h
    const float* __restrict__ h0,     // [B, D]
    const float* __restrict__ Wh)     // [D, D]
{
    extern __shared__ __align__(16) float smem[];
    float* hs   = smem;
    float* part = smem + PART_OFF;

    const int tid  = threadIdx.x;
    const int warp = tid >> 5;
    const int lane = tid & 31;
    const int bid  = blockIdx.x;
    const int jg = bid & 31, bq = bid >> 5;
    const int j0 = jg * 32, b0 = bq * 8;
    const int jq = lane & 7;
    const int kc = (warp << 2) | (lane >> 3);
    const int kb = kc * 32;
    const int kcs = kc ^ (jq << 2);            // swizzled partial column

    u64 wreg[4][16];
#pragma unroll
    for (int jl = 0; jl < 4; ++jl) {
        const int jcol = j0 + jq * 4 + jl;
#pragma unroll
        for (int kk = 0; kk < 16; ++kk) {
            float w0 = Wh[(size_t)(kb + 2 * kk)     * D_DIM + jcol];
            float w1 = Wh[(size_t)(kb + 2 * kk + 1) * D_DIM + jcol];
            wreg[jl][kk] = pack2(w0, w1);
        }
    }

    unsigned* ctr = &g_ctrs[bq];
    const size_t obase = ((size_t)(b0 + warp) * L_DIM) * D_DIM + j0 + lane;

    float xp = out[obase];

    for (int t = 0; t < L_DIM; ++t) {
        const size_t orow = obase + (size_t)t * D_DIM;

        const float* src = (t == 0)
            ? (h0 + (size_t)(b0 + warp) * D_DIM)
            : (out + ((size_t)(b0 + warp) * L_DIM + (t - 1)) * D_DIM);
#pragma unroll
        for (int half = 0; half < 2; ++half) {
            float4 v[4];
#pragma unroll
            for (int m = 0; m < 4; ++m)
                v[m] = __ldcg((const float4*)(src + ((half * 4 + m) * 32 + lane) * 4));
#pragma unroll
            for (int m = 0; m < 4; ++m) {
                int idx = (half * 4 + m) * 32 + lane;
                *(float4*)(hs + warp * HROW_F + (idx >> 3) * 36 + (idx & 7) * 4) = v[m];
            }
        }
        __syncthreads();

        // early xp prefetch for t+1: slot written only by this thread at t+1.
        float xp_next = 0.0f;
        if (t + 1 < L_DIM) xp_next = out[orow + D_DIM];

        u64 acc[8][4];
#pragma unroll
        for (int b = 0; b < 8; ++b)
#pragma unroll
            for (int jl = 0; jl < 4; ++jl) acc[b][jl] = 0ull;

#pragma unroll
        for (int b = 0; b < 8; ++b) {
            const ulonglong2* hb = (const ulonglong2*)(hs + b * HROW_F + kc * 36);
#pragma unroll
            for (int i = 0; i < 8; ++i) {
                ulonglong2 hp = hb[i];
                ffma2(acc[b][0], hp.x, wreg[0][2 * i]);
                ffma2(acc[b][1], hp.x, wreg[1][2 * i]);
                ffma2(acc[b][2], hp.x, wreg[2][2 * i]);
                ffma2(acc[b][3], hp.x, wreg[3][2 * i]);
                ffma2(acc[b][0], hp.y, wreg[0][2 * i + 1]);
                ffma2(acc[b][1], hp.y, wreg[1][2 * i + 1]);
                ffma2(acc[b][2], hp.y, wreg[2][2 * i + 1]);
                ffma2(acc[b][3], hp.y, wreg[3][2 * i + 1]);
            }
        }

#pragma unroll
        for (int b = 0; b < 8; ++b)
#pragma unroll
            for (int jl = 0; jl < 4; ++jl) {
                float lo, hi;
                unpack2(acc[b][jl], lo, hi);
                part[(b * 32 + jq * 4 + jl) * PART_STRIDE + kcs] = lo + hi;
            }

        __syncthreads();

        float s = xp;
        const float* pr = part + (warp * 32 + lane) * PART_STRIDE;
#pragma unroll
        for (int g = 0; g < 8; ++g) {
            float4 p = *(const float4*)(pr + g * 4);
            s += (p.x + p.y) + (p.z + p.w);
        }
        out[orow] = tanhf(s);

        if (t + 1 < L_DIM) {
            __syncthreads();   // all STG issued; also protects hs/part reuse
            if (tid == 0) {
                asm volatile("red.release.gpu.add.u32 [%0], 1;" :: "l"(ctr) : "memory");
                const unsigned target = 32u * (unsigned)(t + 1);
                unsigned v;
                int spins = 0;
                while (true) {
                    asm volatile("ld.acquire.gpu.u32 %0, [%1];" : "=r"(v) : "l"(ctr) : "memory");
                    if (v >= target) break;
                    if (++spins > 8) __nanosleep(32);
                }
            }
            __syncthreads();
        }

        xp = xp_next;
    }
}

// ---------------------------------------------------------------------------
extern "C" void kernel_launch(void* const* d_in, const int* in_sizes, int n_in,
                              void* d_out, int out_size)
{
    (void)in_sizes; (void)n_in; (void)out_size;
    const float* x  = (const float*)d_in[0];
    const float* h0 = (const float*)d_in[1];
    const float* Wx = (const float*)d_in[2];
    const float* Wh = (const float*)d_in[3];
    float* out = (float*)d_out;

    // phase 1: 3xTF32 tensor-core GEMM (cp.async, hoisted addresses, 2 CTA/SM)
    cudaFuncSetAttribute(gemm_mma_kernel,
                         cudaFuncAttributeMaxDynamicSharedMemorySize,
                         P1_SMEM_BYTES);
    dim3 g1(D_DIM / 128, (B_DIM * L_DIM) / 128);
    gemm_mma_kernel<<<g1, 256, P1_SMEM_BYTES>>>(x, Wx, out);

    // phase 2: persistent recurrence
    init_flags_kernel<<<1, 32>>>();
    size_t smem_bytes = (size_t)SMEM2_FLOATS * sizeof(float);
    cudaFuncSetAttribute(rnn_steps_kernel,
                         cudaFuncAttributeMaxDynamicSharedMemorySize,
                         (int)smem_bytes);
    rnn_steps_kernel<<<NB, TPB, smem_bytes>>>(out, h0, Wh);
}